// round 2
// baseline (speedup 1.0000x reference)
#include <cuda_runtime.h>
#include <cuda_bf16.h>

// CenterLoss collapses: the label mask keeps only distmat[b, labels[b]]; all
// other B*(C-1) entries are 0 -> clamped to CLAMP_MIN.
// loss = (sum_b clamp(||x_b - c_{lbl_b}||^2, MIN, MAX)) / B + (C-1)*CLAMP_MIN.

#define BATCH 4096
#define NUM_CLASSES 100000
#define FEAT_DIM 64
#define CLAMP_MIN_F 1e-12f
#define CLAMP_MAX_F 1e12f

#define BLOCK_THREADS 256
#define WARPS_PER_BLOCK (BLOCK_THREADS / 32)
#define NUM_BLOCKS (BATCH / WARPS_PER_BLOCK)   // 512 blocks, 1 warp per row

__device__ float g_partials[NUM_BLOCKS];
__device__ int   g_labels_are_i64;

// ---------------------------------------------------------------------------
// Detect label dtype. Scan int32 words at odd indices 1..4095 (bytes < 16KB:
// in-bounds whether the buffer is 4096 x i32 (16KB) or 4096 x i64 (32KB)).
// int64 labels (< 2^32) -> every odd word is a zero high-half -> OR == 0.
// int32 labels -> odd words are random labels in [0,100000) -> OR != 0
// (P[all 2048 are zero] ~ 0).
// ---------------------------------------------------------------------------
__global__ void __launch_bounds__(256)
detect_label_dtype(const int* __restrict__ l32) {
    __shared__ int s_or[256 / 32];
    int acc = 0;
    for (int i = threadIdx.x; i < 2048; i += 256)
        acc |= l32[2 * i + 1];
    #pragma unroll
    for (int o = 16; o > 0; o >>= 1)
        acc |= __shfl_xor_sync(0xffffffffu, acc, o);
    if ((threadIdx.x & 31) == 0) s_or[threadIdx.x >> 5] = acc;
    __syncthreads();
    if (threadIdx.x == 0) {
        int total = 0;
        #pragma unroll
        for (int w = 0; w < 256 / 32; w++) total |= s_or[w];
        g_labels_are_i64 = (total == 0) ? 1 : 0;
    }
}

__global__ void __launch_bounds__(BLOCK_THREADS)
center_loss_rows(const float* __restrict__ x,
                 const float* __restrict__ centers,
                 const void* __restrict__ labels_raw) {
    const int warp_in_block = threadIdx.x >> 5;
    const int lane = threadIdx.x & 31;
    const int row = blockIdx.x * WARPS_PER_BLOCK + warp_in_block;  // < BATCH

    long long lbl;
    if (g_labels_are_i64) {
        lbl = ((const long long*)labels_raw)[row];
    } else {
        lbl = (long long)((const int*)labels_raw)[row];
    }
    // Crash-proof: clamp into valid range. If the dtype guess were ever wrong
    // we get a finite wrong value (rel_err signal), never an illegal access.
    if (lbl < 0) lbl = 0;
    if (lbl >= NUM_CLASSES) lbl = NUM_CLASSES - 1;

    // 64 floats per row = 32 lanes x float2; fully coalesced 256B rows.
    const float2 xv = reinterpret_cast<const float2*>(x + (size_t)row * FEAT_DIM)[lane];
    const float2 cv = reinterpret_cast<const float2*>(centers + (size_t)lbl * FEAT_DIM)[lane];

    const float d0 = xv.x - cv.x;
    const float d1 = xv.y - cv.y;
    float sum = d0 * d0 + d1 * d1;

    #pragma unroll
    for (int o = 16; o > 0; o >>= 1)
        sum += __shfl_xor_sync(0xffffffffu, sum, o);

    __shared__ float ws[WARPS_PER_BLOCK];
    if (lane == 0)
        ws[warp_in_block] = fminf(fmaxf(sum, CLAMP_MIN_F), CLAMP_MAX_F);
    __syncthreads();

    if (threadIdx.x < WARPS_PER_BLOCK) {
        float v = ws[threadIdx.x];
        #pragma unroll
        for (int o = WARPS_PER_BLOCK / 2; o > 0; o >>= 1)
            v += __shfl_xor_sync(0xffffffffu, v, o);
        if (threadIdx.x == 0)
            g_partials[blockIdx.x] = v;
    }
}

__global__ void __launch_bounds__(NUM_BLOCKS)
center_loss_reduce(float* __restrict__ out) {
    const int tid = threadIdx.x;
    const int lane = tid & 31;
    const int wid = tid >> 5;

    float v = g_partials[tid];
    #pragma unroll
    for (int o = 16; o > 0; o >>= 1)
        v += __shfl_xor_sync(0xffffffffu, v, o);

    __shared__ float ws[NUM_BLOCKS / 32];  // 16
    if (lane == 0) ws[wid] = v;
    __syncthreads();

    if (tid < NUM_BLOCKS / 32) {
        float w = ws[tid];
        #pragma unroll
        for (int o = (NUM_BLOCKS / 32) / 2; o > 0; o >>= 1)
            w += __shfl_xor_sync(0xffffffffu, w, o);
        if (tid == 0) {
            const float mask_term = (float)(NUM_CLASSES - 1) * CLAMP_MIN_F;
            out[0] = w / (float)BATCH + mask_term;
        }
    }
}

extern "C" void kernel_launch(void* const* d_in, const int* in_sizes, int n_in,
                              void* d_out, int out_size) {
    const float* x       = (const float*)d_in[0];
    const float* centers = (const float*)d_in[1];
    const void*  labels  = d_in[2];
    float* out = (float*)d_out;

    detect_label_dtype<<<1, 256>>>((const int*)labels);
    center_loss_rows<<<NUM_BLOCKS, BLOCK_THREADS>>>(x, centers, labels);
    center_loss_reduce<<<1, NUM_BLOCKS>>>(out);
}

// round 5
// speedup vs baseline: 1.4529x; 1.4529x over previous
#include <cuda_runtime.h>
#include <cuda_bf16.h>

// CenterLoss collapses: the label mask keeps only distmat[b, labels[b]]; all
// other B*(C-1) entries are 0 -> clamped to CLAMP_MIN.
// loss = (sum_b clamp(||x_b - c_{lbl_b}||^2, MIN, MAX)) / B + (C-1)*CLAMP_MIN.
//
// LABELS ARE INT32: R3/R4 both failed with the identical rel_err=9.26e-2 when
// hardcoding int64, while R2 (runtime dtype detection) passed -> the detector
// had selected int32. Harness narrows jax int64 to int32.

#define BATCH 4096
#define NUM_CLASSES 100000
#define FEAT_DIM 64
#define CLAMP_MIN_F 1e-12f
#define CLAMP_MAX_F 1e12f

#define BLOCK_THREADS 256
#define WARPS_PER_BLOCK (BLOCK_THREADS / 32)        // 8 rows per block
#define NUM_BLOCKS (BATCH / WARPS_PER_BLOCK)        // 512

__device__ float g_partials[NUM_BLOCKS];

__global__ void __launch_bounds__(BLOCK_THREADS)
center_loss_rows(const float* __restrict__ x,
                 const float* __restrict__ centers,
                 const int* __restrict__ labels) {
    const int warp_in_block = threadIdx.x >> 5;
    const int lane = threadIdx.x & 31;
    const int row = blockIdx.x * WARPS_PER_BLOCK + warp_in_block;   // < BATCH

    int lbl = labels[row];
    // Crash guard (free): a bad label can only give a wrong value, never a fault.
    if (lbl < 0) lbl = 0;
    if (lbl >= NUM_CLASSES) lbl = NUM_CLASSES - 1;

    // 64 floats per row = 32 lanes x float2; fully coalesced 256B rows.
    const float2 xv = reinterpret_cast<const float2*>(x + (size_t)row * FEAT_DIM)[lane];
    const float2 cv = reinterpret_cast<const float2*>(centers + (size_t)lbl * FEAT_DIM)[lane];

    const float d0 = xv.x - cv.x;
    const float d1 = xv.y - cv.y;
    float sum = d0 * d0 + d1 * d1;

    #pragma unroll
    for (int o = 16; o > 0; o >>= 1)
        sum += __shfl_xor_sync(0xffffffffu, sum, o);

    __shared__ float ws[WARPS_PER_BLOCK];
    if (lane == 0)
        ws[warp_in_block] = fminf(fmaxf(sum, CLAMP_MIN_F), CLAMP_MAX_F);  // clip-then-sum
    __syncthreads();

    if (threadIdx.x < WARPS_PER_BLOCK) {
        float v = ws[threadIdx.x];
        #pragma unroll
        for (int o = WARPS_PER_BLOCK / 2; o > 0; o >>= 1)
            v += __shfl_xor_sync(0xffffffffu, v, o);
        if (threadIdx.x == 0)
            g_partials[blockIdx.x] = v;
    }
}

__global__ void __launch_bounds__(NUM_BLOCKS)
center_loss_reduce(float* __restrict__ out) {
    const int tid = threadIdx.x;
    const int lane = tid & 31;
    const int wid = tid >> 5;

    float v = g_partials[tid];
    #pragma unroll
    for (int o = 16; o > 0; o >>= 1)
        v += __shfl_xor_sync(0xffffffffu, v, o);

    __shared__ float ws[NUM_BLOCKS / 32];  // 16 warps
    if (lane == 0) ws[wid] = v;
    __syncthreads();

    if (tid < NUM_BLOCKS / 32) {
        float w = ws[tid];
        #pragma unroll
        for (int o = (NUM_BLOCKS / 32) / 2; o > 0; o >>= 1)
            w += __shfl_xor_sync(0xffffffffu, w, o);
        if (tid == 0) {
            // (C-1) masked zeros per row -> CLAMP_MIN each; /B leaves (C-1)*MIN.
            const float mask_term = (float)(NUM_CLASSES - 1) * CLAMP_MIN_F;
            out[0] = w / (float)BATCH + mask_term;
        }
    }
}

extern "C" void kernel_launch(void* const* d_in, const int* in_sizes, int n_in,
                              void* d_out, int out_size) {
    const float* x       = (const float*)d_in[0];
    const float* centers = (const float*)d_in[1];
    const int*   labels  = (const int*)d_in[2];
    float* out = (float*)d_out;

    center_loss_rows<<<NUM_BLOCKS, BLOCK_THREADS>>>(x, centers, labels);
    center_loss_reduce<<<1, NUM_BLOCKS>>>(out);
}